// round 1
// baseline (speedup 1.0000x reference)
#include <cuda_runtime.h>
#include <math.h>
#include <math_constants.h>

#define BATCH  2
#define SDIM   2048
#define DMODEL 1024
#define NHEADS 16
#define HDIM   64
#define MTOT   (BATCH * SDIM)   // 4096

// ---------------- scratch (no cudaMalloc allowed) ----------------
__device__ float g_q[MTOT * DMODEL];
__device__ float g_k[MTOT * DMODEL];
__device__ float g_v[MTOT * DMODEL];
__device__ float g_attn[MTOT * DMODEL];

// =================================================================
// SGEMM: C[M,N] = A[M,K] @ B[K,N]  (+ bias), all row-major fp32
// tile 128x64, BK=16, 256 threads, 8x4 microtile
// =================================================================
template <bool HAS_BIAS>
__global__ __launch_bounds__(256) void sgemm_kernel(
    const float* __restrict__ A, const float* __restrict__ B,
    const float* __restrict__ bias, float* __restrict__ C,
    int M, int N, int K)
{
    __shared__ float As[16][132];   // transposed A tile, stride 132 (528B, 16B-aligned)
    __shared__ float Bs[16][64];

    const int tid = threadIdx.x;
    const int tx = tid & 15;        // n direction (4 cols)
    const int ty = tid >> 4;        // m direction (8 rows)
    const int m0 = blockIdx.y * 128;
    const int n0 = blockIdx.x * 64;

    float acc[8][4];
#pragma unroll
    for (int i = 0; i < 8; i++)
#pragma unroll
        for (int j = 0; j < 4; j++) acc[i][j] = 0.f;

    const int arow = tid >> 2;           // 0..63
    const int akq  = (tid & 3) * 4;      // 0,4,8,12
    const int brow = tid >> 4;           // 0..15
    const int bnc  = (tid & 15) * 4;

    for (int k0 = 0; k0 < K; k0 += 16) {
#pragma unroll
        for (int p = 0; p < 2; p++) {
            int r = arow + 64 * p;
            float4 v = *(const float4*)&A[(size_t)(m0 + r) * K + k0 + akq];
            As[akq + 0][r] = v.x;
            As[akq + 1][r] = v.y;
            As[akq + 2][r] = v.z;
            As[akq + 3][r] = v.w;
        }
        *(float4*)&Bs[brow][bnc] =
            *(const float4*)&B[(size_t)(k0 + brow) * N + n0 + bnc];
        __syncthreads();

#pragma unroll
        for (int kk = 0; kk < 16; kk++) {
            float a[8], b[4];
#pragma unroll
            for (int i = 0; i < 8; i++) a[i] = As[kk][ty * 8 + i];
#pragma unroll
            for (int j = 0; j < 4; j++) b[j] = Bs[kk][tx * 4 + j];
#pragma unroll
            for (int i = 0; i < 8; i++)
#pragma unroll
                for (int j = 0; j < 4; j++) acc[i][j] += a[i] * b[j];
        }
        __syncthreads();
    }

#pragma unroll
    for (int i = 0; i < 8; i++) {
        float4 v;
        v.x = acc[i][0]; v.y = acc[i][1]; v.z = acc[i][2]; v.w = acc[i][3];
        if (HAS_BIAS) {
            v.x += bias[n0 + tx * 4 + 0];
            v.y += bias[n0 + tx * 4 + 1];
            v.z += bias[n0 + tx * 4 + 2];
            v.w += bias[n0 + tx * 4 + 3];
        }
        *(float4*)&C[(size_t)(m0 + ty * 8 + i) * N + n0 + tx * 4] = v;
    }
}

// =================================================================
// Flash-style causal attention, fp32.
// block: 64 queries of one (b,h). 256 threads, 4x4 microtiles.
// smem: Qs[64][64], Ks[64][65] (reused as Ps), Vs[64][64]  = 49408 B
// =================================================================
__global__ __launch_bounds__(256) void attn_kernel(float* __restrict__ out)
{
    extern __shared__ float sm[];
    float* Qs = sm;                 // [64][64]
    float* Ks = sm + 64 * 64;       // [64][65]  (also holds P after softmax)
    float* Vs = Ks + 64 * 65;       // [64][64]

    const int tid = threadIdx.x;
    const int tx = tid & 15;        // key/col direction (4)
    const int ty = tid >> 4;        // query/row direction (4)
    const int qt = blockIdx.x;
    const int h  = blockIdx.y;
    const int b  = blockIdx.z;
    const int q0 = qt * 64;
    const float scale = 0.03125f;   // 1/sqrt(1024)

    // load Q tile [64 rows][64 d], coalesced float4
    {
        const int dg = (tid & 15) * 4;
#pragma unroll
        for (int p = 0; p < 4; p++) {
            int r = (tid >> 4) + p * 16;
            *(float4*)&Qs[r * 64 + dg] =
                *(const float4*)&g_q[(size_t)(b * SDIM + q0 + r) * DMODEL + h * HDIM + dg];
        }
    }

    float m_r[4], l_r[4], o[4][4];
#pragma unroll
    for (int i = 0; i < 4; i++) {
        m_r[i] = -CUDART_INF_F;
        l_r[i] = 0.f;
#pragma unroll
        for (int j = 0; j < 4; j++) o[i][j] = 0.f;
    }

    for (int kt = 0; kt <= qt; kt++) {
        const int k0 = kt * 64;
        __syncthreads();   // prev iteration's P@V reads of Ks/Vs finished

        // load K (transposed-free, stride 65) and V (stride 64)
        {
            const int dg = (tid & 15) * 4;
#pragma unroll
            for (int p = 0; p < 4; p++) {
                int r = (tid >> 4) + p * 16;
                size_t gofs = (size_t)(b * SDIM + k0 + r) * DMODEL + h * HDIM + dg;
                float4 kv = *(const float4*)&g_k[gofs];
                Ks[r * 65 + dg + 0] = kv.x;
                Ks[r * 65 + dg + 1] = kv.y;
                Ks[r * 65 + dg + 2] = kv.z;
                Ks[r * 65 + dg + 3] = kv.w;
                *(float4*)&Vs[r * 64 + dg] = *(const float4*)&g_v[gofs];
            }
        }
        __syncthreads();

        // scores: s = Q @ K^T  (64x64x64)
        float s[4][4];
#pragma unroll
        for (int i = 0; i < 4; i++)
#pragma unroll
            for (int j = 0; j < 4; j++) s[i][j] = 0.f;

#pragma unroll 8
        for (int kk = 0; kk < 64; kk++) {
            float a[4], bb[4];
#pragma unroll
            for (int i = 0; i < 4; i++) a[i] = Qs[(ty * 4 + i) * 64 + kk];
#pragma unroll
            for (int j = 0; j < 4; j++) bb[j] = Ks[(tx * 4 + j) * 65 + kk];
#pragma unroll
            for (int i = 0; i < 4; i++)
#pragma unroll
                for (int j = 0; j < 4; j++) s[i][j] += a[i] * bb[j];
        }

        // scale + causal mask (only the diagonal tile can be masked)
#pragma unroll
        for (int i = 0; i < 4; i++)
#pragma unroll
            for (int j = 0; j < 4; j++) {
                s[i][j] *= scale;
                if (kt == qt && (tx * 4 + j) > (ty * 4 + i))
                    s[i][j] = -CUDART_INF_F;
            }

        // online softmax (row-wise; rows live on 16 lanes of same ty)
#pragma unroll
        for (int i = 0; i < 4; i++) {
            float mt = fmaxf(fmaxf(s[i][0], s[i][1]), fmaxf(s[i][2], s[i][3]));
#pragma unroll
            for (int off = 8; off >= 1; off >>= 1)
                mt = fmaxf(mt, __shfl_xor_sync(0xffffffffu, mt, off));
            float mnew = fmaxf(m_r[i], mt);
            float alpha = __expf(m_r[i] - mnew);
            m_r[i] = mnew;
            float rs = 0.f;
#pragma unroll
            for (int j = 0; j < 4; j++) {
                s[i][j] = __expf(s[i][j] - mnew);
                rs += s[i][j];
            }
#pragma unroll
            for (int off = 8; off >= 1; off >>= 1)
                rs += __shfl_xor_sync(0xffffffffu, rs, off);
            l_r[i] = l_r[i] * alpha + rs;
#pragma unroll
            for (int j = 0; j < 4; j++) o[i][j] *= alpha;
        }

        __syncthreads();   // everyone done reading Ks as K
        // stage P into Ks region (stride 65)
#pragma unroll
        for (int i = 0; i < 4; i++)
#pragma unroll
            for (int j = 0; j < 4; j++)
                Ks[(ty * 4 + i) * 65 + tx * 4 + j] = s[i][j];
        __syncthreads();

        // o += P @ V  (64x64x64)
#pragma unroll 8
        for (int kk = 0; kk < 64; kk++) {
            float a[4];
#pragma unroll
            for (int i = 0; i < 4; i++) a[i] = Ks[(ty * 4 + i) * 65 + kk];
            float4 v4 = *(const float4*)&Vs[kk * 64 + tx * 4];
#pragma unroll
            for (int i = 0; i < 4; i++) {
                o[i][0] += a[i] * v4.x;
                o[i][1] += a[i] * v4.y;
                o[i][2] += a[i] * v4.z;
                o[i][3] += a[i] * v4.w;
            }
        }
    }

    // epilogue: normalize and store [B,S,H*Dh]
#pragma unroll
    for (int i = 0; i < 4; i++) {
        float inv = 1.f / l_r[i];
        float4 v;
        v.x = o[i][0] * inv; v.y = o[i][1] * inv;
        v.z = o[i][2] * inv; v.w = o[i][3] * inv;
        *(float4*)&out[(size_t)(b * SDIM + q0 + ty * 4 + i) * DMODEL + h * HDIM + tx * 4] = v;
    }
}

// =================================================================
extern "C" void kernel_launch(void* const* d_in, const int* in_sizes, int n_in,
                              void* d_out, int out_size)
{
    const float* x  = (const float*)d_in[0];
    const float* Wq = (const float*)d_in[1];
    const float* Wk = (const float*)d_in[2];
    const float* Wv = (const float*)d_in[3];
    const float* Wo = (const float*)d_in[4];
    const float* bo = (const float*)d_in[5];
    float* out = (float*)d_out;

    float *pq, *pk, *pv, *pa;
    cudaGetSymbolAddress((void**)&pq, g_q);
    cudaGetSymbolAddress((void**)&pk, g_k);
    cudaGetSymbolAddress((void**)&pv, g_v);
    cudaGetSymbolAddress((void**)&pa, g_attn);

    dim3 ggrid(DMODEL / 64, MTOT / 128);   // (16, 32)

    sgemm_kernel<false><<<ggrid, 256>>>(x, Wq, nullptr, pq, MTOT, DMODEL, DMODEL);
    sgemm_kernel<false><<<ggrid, 256>>>(x, Wk, nullptr, pk, MTOT, DMODEL, DMODEL);
    sgemm_kernel<false><<<ggrid, 256>>>(x, Wv, nullptr, pv, MTOT, DMODEL, DMODEL);

    const int smem = (64 * 64 + 64 * 65 + 64 * 64) * (int)sizeof(float); // 49408
    cudaFuncSetAttribute(attn_kernel, cudaFuncAttributeMaxDynamicSharedMemorySize, smem);
    dim3 agrid(SDIM / 64, NHEADS, BATCH);  // (32, 16, 2)
    attn_kernel<<<agrid, 256, smem>>>(pa);

    sgemm_kernel<true><<<ggrid, 256>>>(pa, Wo, bo, out, MTOT, DMODEL, DMODEL);
}

// round 3
// speedup vs baseline: 1.4591x; 1.4591x over previous
#include <cuda_runtime.h>
#include <cuda_bf16.h>
#include <math.h>
#include <math_constants.h>
#include <stdint.h>

#define BATCH  2
#define SDIM   2048
#define DMODEL 1024
#define NHEADS 16
#define HDIM   64
#define MTOT   (BATCH * SDIM)   // 4096

// ---------------- scratch (no cudaMalloc allowed) ----------------
__device__ float g_q[MTOT * DMODEL];
__device__ float g_k[MTOT * DMODEL];
__device__ float g_v[MTOT * DMODEL];
__device__ float g_attn[MTOT * DMODEL];
__device__ __nv_bfloat16 g_xhi[MTOT * DMODEL];
__device__ __nv_bfloat16 g_xlo[MTOT * DMODEL];
__device__ __nv_bfloat16 g_ahi[MTOT * DMODEL];
__device__ __nv_bfloat16 g_alo[MTOT * DMODEL];
__device__ __nv_bfloat16 g_whi[4 * DMODEL * DMODEL];   // W^T, [N,K] per slot
__device__ __nv_bfloat16 g_wlo[4 * DMODEL * DMODEL];

// ---------------- PTX helpers (compute_103-safe: sm_80-era ops only) ----
__device__ __forceinline__ uint32_t smem_u32(const void* p) {
    uint32_t a;
    asm("{ .reg .u64 t; cvta.to.shared.u64 t, %1; cvt.u32.u64 %0, t; }"
        : "=r"(a) : "l"(p));
    return a;
}

__device__ __forceinline__ void cp16(uint32_t dst, const void* src) {
    asm volatile("cp.async.ca.shared.global [%0], [%1], 16;"
                 :: "r"(dst), "l"(src) : "memory");
}
#define CP_COMMIT() asm volatile("cp.async.commit_group;" ::: "memory")
#define CP_WAIT1()  asm volatile("cp.async.wait_group 1;" ::: "memory")
#define CP_WAIT0()  asm volatile("cp.async.wait_group 0;" ::: "memory")

__device__ __forceinline__ void ldm_x4(uint32_t& r0, uint32_t& r1,
                                       uint32_t& r2, uint32_t& r3, uint32_t addr) {
    asm volatile("ldmatrix.sync.aligned.m8n8.x4.shared.b16 {%0,%1,%2,%3}, [%4];"
                 : "=r"(r0), "=r"(r1), "=r"(r2), "=r"(r3) : "r"(addr));
}

__device__ __forceinline__ void mma_bf16(float* d, const uint32_t* a,
                                         uint32_t b0, uint32_t b1) {
    asm volatile(
        "mma.sync.aligned.m16n8k16.row.col.f32.bf16.bf16.f32 "
        "{%0,%1,%2,%3}, {%4,%5,%6,%7}, {%8,%9}, {%0,%1,%2,%3};"
        : "+f"(d[0]), "+f"(d[1]), "+f"(d[2]), "+f"(d[3])
        : "r"(a[0]), "r"(a[1]), "r"(a[2]), "r"(a[3]), "r"(b0), "r"(b1));
}

// =================================================================
// split fp32 -> (hi, lo) bf16, elementwise (vector-4)
// =================================================================
__global__ __launch_bounds__(256) void split_kernel(
    const float* __restrict__ in, __nv_bfloat16* __restrict__ hi,
    __nv_bfloat16* __restrict__ lo, int n)
{
    int i = (blockIdx.x * 256 + threadIdx.x) * 4;
    if (i >= n) return;
    float4 v = *(const float4*)(in + i);
    __nv_bfloat16 h0 = __float2bfloat16(v.x);
    __nv_bfloat16 h1 = __float2bfloat16(v.y);
    __nv_bfloat16 h2 = __float2bfloat16(v.z);
    __nv_bfloat16 h3 = __float2bfloat16(v.w);
    __nv_bfloat16 l0 = __float2bfloat16(v.x - __bfloat162float(h0));
    __nv_bfloat16 l1 = __float2bfloat16(v.y - __bfloat162float(h1));
    __nv_bfloat16 l2 = __float2bfloat16(v.z - __bfloat162float(h2));
    __nv_bfloat16 l3 = __float2bfloat16(v.w - __bfloat162float(h3));
    hi[i + 0] = h0; hi[i + 1] = h1; hi[i + 2] = h2; hi[i + 3] = h3;
    lo[i + 0] = l0; lo[i + 1] = l1; lo[i + 2] = l2; lo[i + 3] = l3;
}

// =================================================================
// transpose + split: W[K,N] fp32 -> Wt hi/lo [N,K] bf16
// =================================================================
__global__ __launch_bounds__(256) void tsplit_kernel(
    const float* __restrict__ W, __nv_bfloat16* __restrict__ hi,
    __nv_bfloat16* __restrict__ lo)
{
    __shared__ float t[32][33];
    const int nt = blockIdx.x * 32, kt = blockIdx.y * 32;
    const int x = threadIdx.x, y = threadIdx.y;
#pragma unroll
    for (int i = 0; i < 4; i++)
        t[y + i * 8][x] = W[(size_t)(kt + y + i * 8) * DMODEL + nt + x];  // t[k][n]
    __syncthreads();
#pragma unroll
    for (int i = 0; i < 4; i++) {
        float v = t[x][y + i * 8];                 // k = kt+x, n = nt+y+i*8
        __nv_bfloat16 h = __float2bfloat16(v);
        __nv_bfloat16 l = __float2bfloat16(v - __bfloat162float(h));
        size_t o = (size_t)(nt + y + i * 8) * DMODEL + kt + x;
        hi[o] = h; lo[o] = l;
    }
}

// =================================================================
// split-bf16 GEMM via mma.sync (HMMA), C = (Ahi+Alo)@(Bhi+Blo)^T (+bias)
// A: [M,K] K-major bf16.  B: [N,K] K-major bf16 == mma "col" layout.
// CTA 128x64, BK=32, 8 warps (4m x 2n), warp tile 32x32.
// Smem rows padded to 40 halves (80B) -> conflict-free ldmatrix.
// 2-stage cp.async pipeline.
// =================================================================
#define PAD 40
#define ST_A   (128 * PAD * 2)            // 10240 B per A matrix
#define ST_B   (64 * PAD * 2)             // 5120 B per B matrix
#define ST_SZ  (2 * ST_A + 2 * ST_B)      // 30720 B per stage
#define OFF_AHI 0
#define OFF_ALO ST_A
#define OFF_BHI (2 * ST_A)
#define OFF_BLO (2 * ST_A + ST_B)

template <bool HAS_BIAS>
__global__ __launch_bounds__(256) void gemm_mma_kernel(
    const __nv_bfloat16* __restrict__ Ahi, const __nv_bfloat16* __restrict__ Alo,
    const __nv_bfloat16* __restrict__ Bhi, const __nv_bfloat16* __restrict__ Blo,
    const float* __restrict__ bias, float* __restrict__ C, int M, int N, int K)
{
    extern __shared__ __align__(128) char smem[];
    const uint32_t sb = smem_u32(smem);
    const int tid = threadIdx.x;
    const int wid = tid >> 5, lane = tid & 31;
    const int wm = wid & 3, wn = wid >> 2;          // warp tile origin
    const int m0 = blockIdx.y * 128, n0 = blockIdx.x * 64;

    const int lrow = lane & 15;
    const int lcolb = (lane >> 4) * 16;             // byte offset within row (8 halves)

    float acc[2][4][4];
#pragma unroll
    for (int mt = 0; mt < 2; mt++)
#pragma unroll
        for (int nt = 0; nt < 4; nt++)
#pragma unroll
            for (int j = 0; j < 4; j++) acc[mt][nt][j] = 0.f;

    const int nchunks = K >> 5;   // BK=32

    // ---- async load of one stage ----
    auto issue = [&](int c) {
        const int k0 = c << 5;
        const uint32_t st = sb + (uint32_t)((c & 1) * ST_SZ);
        // A: 128 rows x 4 chunks of 8 halves, x2 matrices
#pragma unroll
        for (int i = 0; i < 2; i++) {
            int idx = tid + i * 256;                 // 0..511
            int r = idx >> 2, kc = idx & 3;
            size_t go = (size_t)(m0 + r) * K + k0 + kc * 8;
            uint32_t so = (uint32_t)(r * 80 + kc * 16);
            cp16(st + OFF_AHI + so, Ahi + go);
            cp16(st + OFF_ALO + so, Alo + go);
        }
        // B: 64 rows x 4 chunks, x2 matrices
        {
            int r = tid >> 2, kc = tid & 3;
            size_t go = (size_t)(n0 + r) * K + k0 + kc * 8;
            uint32_t so = (uint32_t)(r * 80 + kc * 16);
            cp16(st + OFF_BHI + so, Bhi + go);
            cp16(st + OFF_BLO + so, Blo + go);
        }
        CP_COMMIT();
    };

    issue(0);
    if (nchunks > 1) issue(1);

    for (int c = 0; c < nchunks; c++) {
        if (c + 1 < nchunks) CP_WAIT1(); else CP_WAIT0();
        __syncthreads();

        const uint32_t st = sb + (uint32_t)((c & 1) * ST_SZ);
        const uint32_t aRowHi = st + OFF_AHI + (uint32_t)((wm * 32 + lrow) * 80) + lcolb;
        const uint32_t aRowLo = st + OFF_ALO + (uint32_t)((wm * 32 + lrow) * 80) + lcolb;
        const uint32_t bRowHi = st + OFF_BHI + (uint32_t)((wn * 32 + lrow) * 80) + lcolb;
        const uint32_t bRowLo = st + OFF_BLO + (uint32_t)((wn * 32 + lrow) * 80) + lcolb;

#pragma unroll
        for (int ks = 0; ks < 2; ks++) {            // two k16 steps per BK=32
            const uint32_t kb = ks * 32;            // 16 halves = 32 B
            uint32_t ah[2][4], al[2][4];
#pragma unroll
            for (int mt = 0; mt < 2; mt++) {
                ldm_x4(ah[mt][0], ah[mt][1], ah[mt][2], ah[mt][3],
                       aRowHi + (uint32_t)(mt * 16 * 80) + kb);
                ldm_x4(al[mt][0], al[mt][1], al[mt][2], al[mt][3],
                       aRowLo + (uint32_t)(mt * 16 * 80) + kb);
            }
            // B frags: group g covers n-tiles 2g, 2g+1
            uint32_t bh[4][2], bl[4][2];
#pragma unroll
            for (int g = 0; g < 2; g++) {
                uint32_t r0, r1, r2, r3;
                ldm_x4(r0, r1, r2, r3, bRowHi + (uint32_t)(g * 16 * 80) + kb);
                bh[2 * g + 0][0] = r0; bh[2 * g + 0][1] = r2;
                bh[2 * g + 1][0] = r1; bh[2 * g + 1][1] = r3;
                ldm_x4(r0, r1, r2, r3, bRowLo + (uint32_t)(g * 16 * 80) + kb);
                bl[2 * g + 0][0] = r0; bl[2 * g + 0][1] = r2;
                bl[2 * g + 1][0] = r1; bl[2 * g + 1][1] = r3;
            }
#pragma unroll
            for (int mt = 0; mt < 2; mt++)
#pragma unroll
                for (int nt = 0; nt < 4; nt++) {
                    mma_bf16(acc[mt][nt], ah[mt], bh[nt][0], bh[nt][1]);
                    mma_bf16(acc[mt][nt], ah[mt], bl[nt][0], bl[nt][1]);
                    mma_bf16(acc[mt][nt], al[mt], bh[nt][0], bh[nt][1]);
                }
        }
        __syncthreads();
        if (c + 2 < nchunks) issue(c + 2);
    }

    // ---- epilogue: c-frag layout row = lane/4 (+8), col = 2*(lane%4)+{0,1}
    const int rbase = m0 + wm * 32 + (lane >> 2);
    const int cbase = n0 + wn * 32 + 2 * (lane & 3);
#pragma unroll
    for (int mt = 0; mt < 2; mt++)
#pragma unroll
        for (int nt = 0; nt < 4; nt++) {
            int col = cbase + nt * 8;
            float b0 = 0.f, b1 = 0.f;
            if (HAS_BIAS) { b0 = bias[col]; b1 = bias[col + 1]; }
            int r0 = rbase + mt * 16;
            float2 v0 = { acc[mt][nt][0] + b0, acc[mt][nt][1] + b1 };
            float2 v1 = { acc[mt][nt][2] + b0, acc[mt][nt][3] + b1 };
            *(float2*)&C[(size_t)r0 * N + col] = v0;
            *(float2*)&C[(size_t)(r0 + 8) * N + col] = v1;
        }
}

// =================================================================
// Flash-style causal attention, fp32 (unchanged).
// =================================================================
__global__ __launch_bounds__(256) void attn_kernel(float* __restrict__ out)
{
    extern __shared__ float sm[];
    float* Qs = sm;                 // [64][64]
    float* Ks = sm + 64 * 64;       // [64][65]  (also holds P after softmax)
    float* Vs = Ks + 64 * 65;       // [64][64]

    const int tid = threadIdx.x;
    const int tx = tid & 15;
    const int ty = tid >> 4;
    const int qt = blockIdx.x;
    const int h  = blockIdx.y;
    const int b  = blockIdx.z;
    const int q0 = qt * 64;
    const float scale = 0.03125f;

    {
        const int dg = (tid & 15) * 4;
#pragma unroll
        for (int p = 0; p < 4; p++) {
            int r = (tid >> 4) + p * 16;
            *(float4*)&Qs[r * 64 + dg] =
                *(const float4*)&g_q[(size_t)(b * SDIM + q0 + r) * DMODEL + h * HDIM + dg];
        }
    }

    float m_r[4], l_r[4], o[4][4];
#pragma unroll
    for (int i = 0; i < 4; i++) {
        m_r[i] = -CUDART_INF_F;
        l_r[i] = 0.f;
#pragma unroll
        for (int j = 0; j < 4; j++) o[i][j] = 0.f;
    }

    for (int kt = 0; kt <= qt; kt++) {
        const int k0 = kt * 64;
        __syncthreads();
        {
            const int dg = (tid & 15) * 4;
#pragma unroll
            for (int p = 0; p < 4; p++) {
                int r = (tid >> 4) + p * 16;
                size_t gofs = (size_t)(b * SDIM + k0 + r) * DMODEL + h * HDIM + dg;
                float4 kv = *(const float4*)&g_k[gofs];
                Ks[r * 65 + dg + 0] = kv.x;
                Ks[r * 65 + dg + 1] = kv.y;
                Ks[r * 65 + dg + 2] = kv.z;
                Ks[r * 65 + dg + 3] = kv.w;
                *(float4*)&Vs[r * 64 + dg] = *(const float4*)&g_v[gofs];
            }
        }
        __syncthreads();

        float s[4][4];
#pragma unroll
        for (int i = 0; i < 4; i++)
#pragma unroll
            for (int j = 0; j < 4; j++) s[i][j] = 0.f;

#pragma unroll 8
        for (int kk = 0; kk < 64; kk++) {
            float a[4], bb[4];
#pragma unroll
            for (int i = 0; i < 4; i++) a[i] = Qs[(ty * 4 + i) * 64 + kk];
#pragma unroll
            for (int j = 0; j < 4; j++) bb[j] = Ks[(tx * 4 + j) * 65 + kk];
#pragma unroll
            for (int i = 0; i < 4; i++)
#pragma unroll
                for (int j = 0; j < 4; j++) s[i][j] += a[i] * bb[j];
        }

#pragma unroll
        for (int i = 0; i < 4; i++)
#pragma unroll
            for (int j = 0; j < 4; j++) {
                s[i][j] *= scale;
                if (kt == qt && (tx * 4 + j) > (ty * 4 + i))
                    s[i][j] = -CUDART_INF_F;
            }

#pragma unroll
        for (int i = 0; i < 4; i++) {
            float mt = fmaxf(fmaxf(s[i][0], s[i][1]), fmaxf(s[i][2], s[i][3]));
#pragma unroll
            for (int off = 8; off >= 1; off >>= 1)
                mt = fmaxf(mt, __shfl_xor_sync(0xffffffffu, mt, off));
            float mnew = fmaxf(m_r[i], mt);
            float alpha = __expf(m_r[i] - mnew);
            m_r[i] = mnew;
            float rs = 0.f;
#pragma unroll
            for (int j = 0; j < 4; j++) {
                s[i][j] = __expf(s[i][j] - mnew);
                rs += s[i][j];
            }
#pragma unroll
            for (int off = 8; off >= 1; off >>= 1)
                rs += __shfl_xor_sync(0xffffffffu, rs, off);
            l_r[i] = l_r[i] * alpha + rs;
#pragma unroll
            for (int j = 0; j < 4; j++) o[i][j] *= alpha;
        }

        __syncthreads();
#pragma unroll
        for (int i = 0; i < 4; i++)
#pragma unroll
            for (int j = 0; j < 4; j++)
                Ks[(ty * 4 + i) * 65 + tx * 4 + j] = s[i][j];
        __syncthreads();

#pragma unroll 8
        for (int kk = 0; kk < 64; kk++) {
            float a[4];
#pragma unroll
            for (int i = 0; i < 4; i++) a[i] = Ks[(ty * 4 + i) * 65 + kk];
            float4 v4 = *(const float4*)&Vs[kk * 64 + tx * 4];
#pragma unroll
            for (int i = 0; i < 4; i++) {
                o[i][0] += a[i] * v4.x;
                o[i][1] += a[i] * v4.y;
                o[i][2] += a[i] * v4.z;
                o[i][3] += a[i] * v4.w;
            }
        }
    }

#pragma unroll
    for (int i = 0; i < 4; i++) {
        float inv = 1.f / l_r[i];
        float4 v;
        v.x = o[i][0] * inv; v.y = o[i][1] * inv;
        v.z = o[i][2] * inv; v.w = o[i][3] * inv;
        *(float4*)&out[(size_t)(b * SDIM + q0 + ty * 4 + i) * DMODEL + h * HDIM + tx * 4] = v;
    }
}

// =================================================================
extern "C" void kernel_launch(void* const* d_in, const int* in_sizes, int n_in,
                              void* d_out, int out_size)
{
    const float* x  = (const float*)d_in[0];
    const float* Wq = (const float*)d_in[1];
    const float* Wk = (const float*)d_in[2];
    const float* Wv = (const float*)d_in[3];
    const float* Wo = (const float*)d_in[4];
    const float* bo = (const float*)d_in[5];
    float* out = (float*)d_out;

    float *pq, *pk, *pv, *pa;
    __nv_bfloat16 *pxh, *pxl, *pah, *pal, *pwh, *pwl;
    cudaGetSymbolAddress((void**)&pq, g_q);
    cudaGetSymbolAddress((void**)&pk, g_k);
    cudaGetSymbolAddress((void**)&pv, g_v);
    cudaGetSymbolAddress((void**)&pa, g_attn);
    cudaGetSymbolAddress((void**)&pxh, g_xhi);
    cudaGetSymbolAddress((void**)&pxl, g_xlo);
    cudaGetSymbolAddress((void**)&pah, g_ahi);
    cudaGetSymbolAddress((void**)&pal, g_alo);
    cudaGetSymbolAddress((void**)&pwh, g_whi);
    cudaGetSymbolAddress((void**)&pwl, g_wlo);

    const int NEL = MTOT * DMODEL;
    const int WEL = DMODEL * DMODEL;

    split_kernel<<<NEL / (256 * 4), 256>>>(x, pxh, pxl, NEL);
    dim3 tgrid(DMODEL / 32, DMODEL / 32), tblk(32, 8);
    tsplit_kernel<<<tgrid, tblk>>>(Wq, pwh + 0 * WEL, pwl + 0 * WEL);
    tsplit_kernel<<<tgrid, tblk>>>(Wk, pwh + 1 * WEL, pwl + 1 * WEL);
    tsplit_kernel<<<tgrid, tblk>>>(Wv, pwh + 2 * WEL, pwl + 2 * WEL);
    tsplit_kernel<<<tgrid, tblk>>>(Wo, pwh + 3 * WEL, pwl + 3 * WEL);

    const int gsmem = 2 * ST_SZ;   // 61440
    cudaFuncSetAttribute(gemm_mma_kernel<false>,
                         cudaFuncAttributeMaxDynamicSharedMemorySize, gsmem);
    cudaFuncSetAttribute(gemm_mma_kernel<true>,
                         cudaFuncAttributeMaxDynamicSharedMemorySize, gsmem);

    dim3 ggrid(DMODEL / 64, MTOT / 128);  // (16, 32)
    gemm_mma_kernel<false><<<ggrid, 256, gsmem>>>(pxh, pxl, pwh + 0 * WEL, pwl + 0 * WEL,
                                                  nullptr, pq, MTOT, DMODEL, DMODEL);
    gemm_mma_kernel<false><<<ggrid, 256, gsmem>>>(pxh, pxl, pwh + 1 * WEL, pwl + 1 * WEL,
                                                  nullptr, pk, MTOT, DMODEL, DMODEL);
    gemm_mma_kernel<false><<<ggrid, 256, gsmem>>>(pxh, pxl, pwh + 2 * WEL, pwl + 2 * WEL,
                                                  nullptr, pv, MTOT, DMODEL, DMODEL);

    const int asmem = (64 * 64 + 64 * 65 + 64 * 64) * (int)sizeof(float); // 49408
    cudaFuncSetAttribute(attn_kernel, cudaFuncAttributeMaxDynamicSharedMemorySize, asmem);
    dim3 agrid(SDIM / 64, NHEADS, BATCH);
    attn_kernel<<<agrid, 256, asmem>>>(pa);

    split_kernel<<<NEL / (256 * 4), 256>>>(pa, pah, pal, NEL);
    gemm_mma_kernel<true><<<ggrid, 256, gsmem>>>(pah, pal, pwh + 3 * WEL, pwl + 3 * WEL,
                                                 bo, out, MTOT, DMODEL, DMODEL);
}

// round 4
// speedup vs baseline: 2.6530x; 1.8183x over previous
#include <cuda_runtime.h>
#include <cuda_bf16.h>
#include <math.h>
#include <math_constants.h>
#include <stdint.h>

#define BATCH  2
#define SDIM   2048
#define DMODEL 1024
#define NHEADS 16
#define HDIM   64
#define MTOT   (BATCH * SDIM)          // 4096
#define SLOTSZ (MTOT * DMODEL)

// ---------------- scratch ----------------
__device__ __nv_bfloat16 g_xhi[SLOTSZ];
__device__ __nv_bfloat16 g_xlo[SLOTSZ];
__device__ __nv_bfloat16 g_qkvh[3 * SLOTSZ];   // slot 0=Q,1=K,2=V  [M,1024]
__device__ __nv_bfloat16 g_qkvl[3 * SLOTSZ];
__device__ __nv_bfloat16 g_ah[SLOTSZ];         // attention out hi/lo
__device__ __nv_bfloat16 g_al[SLOTSZ];
__device__ __nv_bfloat16 g_whi[4 * DMODEL * DMODEL];  // W^T slots: q,k,v,o
__device__ __nv_bfloat16 g_wlo[4 * DMODEL * DMODEL];

// ---------------- PTX helpers (sm_80-era, compute_103-safe) ----------
__device__ __forceinline__ uint32_t smem_u32(const void* p) {
    uint32_t a;
    asm("{ .reg .u64 t; cvta.to.shared.u64 t, %1; cvt.u32.u64 %0, t; }"
        : "=r"(a) : "l"(p));
    return a;
}
__device__ __forceinline__ void cp16(uint32_t dst, const void* src) {
    asm volatile("cp.async.ca.shared.global [%0], [%1], 16;"
                 :: "r"(dst), "l"(src) : "memory");
}
#define CP_COMMIT() asm volatile("cp.async.commit_group;" ::: "memory")
#define CP_WAIT1()  asm volatile("cp.async.wait_group 1;" ::: "memory")
#define CP_WAIT0()  asm volatile("cp.async.wait_group 0;" ::: "memory")

__device__ __forceinline__ void ldm_x4(uint32_t& r0, uint32_t& r1,
                                       uint32_t& r2, uint32_t& r3, uint32_t a) {
    asm volatile("ldmatrix.sync.aligned.m8n8.x4.shared.b16 {%0,%1,%2,%3}, [%4];"
                 : "=r"(r0), "=r"(r1), "=r"(r2), "=r"(r3) : "r"(a));
}
__device__ __forceinline__ void ldm_x4t(uint32_t& r0, uint32_t& r1,
                                        uint32_t& r2, uint32_t& r3, uint32_t a) {
    asm volatile("ldmatrix.sync.aligned.m8n8.x4.trans.shared.b16 {%0,%1,%2,%3}, [%4];"
                 : "=r"(r0), "=r"(r1), "=r"(r2), "=r"(r3) : "r"(a));
}
__device__ __forceinline__ void mma_bf16(float* d, const uint32_t* a,
                                         uint32_t b0, uint32_t b1) {
    asm volatile(
        "mma.sync.aligned.m16n8k16.row.col.f32.bf16.bf16.f32 "
        "{%0,%1,%2,%3}, {%4,%5,%6,%7}, {%8,%9}, {%0,%1,%2,%3};"
        : "+f"(d[0]), "+f"(d[1]), "+f"(d[2]), "+f"(d[3])
        : "r"(a[0]), "r"(a[1]), "r"(a[2]), "r"(a[3]), "r"(b0), "r"(b1));
}
__device__ __forceinline__ uint32_t packbf(float lo, float hi) {
    __nv_bfloat162 t = __floats2bfloat162_rn(lo, hi);   // x=lo half
    return *(uint32_t*)&t;
}

// =================================================================
// split fp32 -> (hi, lo) bf16
// =================================================================
__global__ __launch_bounds__(256) void split_kernel(
    const float* __restrict__ in, __nv_bfloat16* __restrict__ hi,
    __nv_bfloat16* __restrict__ lo, int n)
{
    int i = (blockIdx.x * 256 + threadIdx.x) * 4;
    if (i >= n) return;
    float4 v = *(const float4*)(in + i);
    __nv_bfloat16 h0 = __float2bfloat16(v.x), h1 = __float2bfloat16(v.y);
    __nv_bfloat16 h2 = __float2bfloat16(v.z), h3 = __float2bfloat16(v.w);
    hi[i + 0] = h0; hi[i + 1] = h1; hi[i + 2] = h2; hi[i + 3] = h3;
    lo[i + 0] = __float2bfloat16(v.x - __bfloat162float(h0));
    lo[i + 1] = __float2bfloat16(v.y - __bfloat162float(h1));
    lo[i + 2] = __float2bfloat16(v.z - __bfloat162float(h2));
    lo[i + 3] = __float2bfloat16(v.w - __bfloat162float(h3));
}

// =================================================================
// transpose + split: W[K,N] fp32 -> W^T hi/lo [N,K] bf16
// =================================================================
__global__ __launch_bounds__(256) void tsplit_kernel(
    const float* __restrict__ W, __nv_bfloat16* __restrict__ hi,
    __nv_bfloat16* __restrict__ lo)
{
    __shared__ float t[32][33];
    const int nt = blockIdx.x * 32, kt = blockIdx.y * 32;
    const int x = threadIdx.x, y = threadIdx.y;
#pragma unroll
    for (int i = 0; i < 4; i++)
        t[y + i * 8][x] = W[(size_t)(kt + y + i * 8) * DMODEL + nt + x];
    __syncthreads();
#pragma unroll
    for (int i = 0; i < 4; i++) {
        float v = t[x][y + i * 8];
        __nv_bfloat16 h = __float2bfloat16(v);
        size_t o = (size_t)(nt + y + i * 8) * DMODEL + kt + x;
        hi[o] = h; lo[o] = __float2bfloat16(v - __bfloat162float(h));
    }
}

// =================================================================
// split-bf16 GEMM via mma.sync.  MODE 0: fp32 out + bias.
// MODE 1: split-bf16 out with QKV slot remap (N=3072).
// CTA 128x64, BK=32, 8 warps (4m x 2n), 2-stage cp.async.
// =================================================================
#define PAD80 80
#define ST_A   (128 * PAD80)
#define ST_B   (64 * PAD80)
#define ST_SZ  (2 * ST_A + 2 * ST_B)
#define OFF_ALOW ST_A
#define OFF_BHI (2 * ST_A)
#define OFF_BLO (2 * ST_A + ST_B)

template <int MODE>
__global__ __launch_bounds__(256) void gemm_mma_kernel(
    const __nv_bfloat16* __restrict__ Ahi, const __nv_bfloat16* __restrict__ Alo,
    const __nv_bfloat16* __restrict__ Bhi, const __nv_bfloat16* __restrict__ Blo,
    const float* __restrict__ bias, float* __restrict__ C,
    __nv_bfloat16* __restrict__ Ch, __nv_bfloat16* __restrict__ Cl,
    int M, int N, int K)
{
    extern __shared__ __align__(128) char smem[];
    const uint32_t sb = smem_u32(smem);
    const int tid = threadIdx.x;
    const int wid = tid >> 5, lane = tid & 31;
    const int wm = wid & 3, wn = wid >> 2;
    const int m0 = blockIdx.y * 128, n0 = blockIdx.x * 64;
    const int lrow = lane & 15, lcolb = (lane >> 4) * 16;

    float acc[2][4][4];
#pragma unroll
    for (int mt = 0; mt < 2; mt++)
#pragma unroll
        for (int nt = 0; nt < 4; nt++)
#pragma unroll
            for (int j = 0; j < 4; j++) acc[mt][nt][j] = 0.f;

    const int nchunks = K >> 5;

    auto issue = [&](int c) {
        const int k0 = c << 5;
        const uint32_t st = sb + (uint32_t)((c & 1) * ST_SZ);
#pragma unroll
        for (int i = 0; i < 2; i++) {
            int idx = tid + i * 256;
            int r = idx >> 2, kc = idx & 3;
            size_t go = (size_t)(m0 + r) * K + k0 + kc * 8;
            uint32_t so = (uint32_t)(r * 80 + kc * 16);
            cp16(st + so, Ahi + go);
            cp16(st + OFF_ALOW + so, Alo + go);
        }
        {
            int r = tid >> 2, kc = tid & 3;
            size_t go = (size_t)(n0 + r) * K + k0 + kc * 8;
            uint32_t so = (uint32_t)(r * 80 + kc * 16);
            cp16(st + OFF_BHI + so, Bhi + go);
            cp16(st + OFF_BLO + so, Blo + go);
        }
        CP_COMMIT();
    };

    issue(0);
    issue(1);

    for (int c = 0; c < nchunks; c++) {
        if (c + 1 < nchunks) CP_WAIT1(); else CP_WAIT0();
        __syncthreads();

        const uint32_t st = sb + (uint32_t)((c & 1) * ST_SZ);
        const uint32_t aHi = st + (uint32_t)((wm * 32 + lrow) * 80) + lcolb;
        const uint32_t aLo = aHi + OFF_ALOW;
        const uint32_t bHi = st + OFF_BHI + (uint32_t)((wn * 32 + lrow) * 80) + lcolb;
        const uint32_t bLo = bHi + ST_B;

#pragma unroll
        for (int ks = 0; ks < 2; ks++) {
            const uint32_t kb = ks * 32;
            uint32_t ah[2][4], al[2][4];
#pragma unroll
            for (int mt = 0; mt < 2; mt++) {
                ldm_x4(ah[mt][0], ah[mt][1], ah[mt][2], ah[mt][3],
                       aHi + (uint32_t)(mt * 16 * 80) + kb);
                ldm_x4(al[mt][0], al[mt][1], al[mt][2], al[mt][3],
                       aLo + (uint32_t)(mt * 16 * 80) + kb);
            }
            uint32_t bh[4][2], bl[4][2];
#pragma unroll
            for (int g = 0; g < 2; g++) {
                uint32_t r0, r1, r2, r3;
                ldm_x4(r0, r1, r2, r3, bHi + (uint32_t)(g * 16 * 80) + kb);
                bh[2 * g + 0][0] = r0; bh[2 * g + 0][1] = r2;
                bh[2 * g + 1][0] = r1; bh[2 * g + 1][1] = r3;
                ldm_x4(r0, r1, r2, r3, bLo + (uint32_t)(g * 16 * 80) + kb);
                bl[2 * g + 0][0] = r0; bl[2 * g + 0][1] = r2;
                bl[2 * g + 1][0] = r1; bl[2 * g + 1][1] = r3;
            }
#pragma unroll
            for (int mt = 0; mt < 2; mt++)
#pragma unroll
                for (int nt = 0; nt < 4; nt++) {
                    mma_bf16(acc[mt][nt], ah[mt], bh[nt][0], bh[nt][1]);
                    mma_bf16(acc[mt][nt], ah[mt], bl[nt][0], bl[nt][1]);
                    mma_bf16(acc[mt][nt], al[mt], bh[nt][0], bh[nt][1]);
                }
        }
        __syncthreads();
        if (c + 2 < nchunks) issue(c + 2);
    }

    const int rbase = m0 + wm * 32 + (lane >> 2);
    const int cb0 = n0 + wn * 32 + 2 * (lane & 3);
#pragma unroll
    for (int mt = 0; mt < 2; mt++)
#pragma unroll
        for (int nt = 0; nt < 4; nt++) {
            int col = cb0 + nt * 8;
            int r0 = rbase + mt * 16;
            if (MODE == 0) {
                float b0 = bias[col], b1 = bias[col + 1];
                float2 v0 = { acc[mt][nt][0] + b0, acc[mt][nt][1] + b1 };
                float2 v1 = { acc[mt][nt][2] + b0, acc[mt][nt][3] + b1 };
                *(float2*)&C[(size_t)r0 * N + col] = v0;
                *(float2*)&C[(size_t)(r0 + 8) * N + col] = v1;
            } else {
                int slot = col >> 10, coll = col & 1023;
                size_t ob = (size_t)slot * SLOTSZ + (size_t)coll;
#pragma unroll
                for (int half = 0; half < 2; half++) {
                    int rr = r0 + half * 8;
                    float v0 = acc[mt][nt][2 * half], v1 = acc[mt][nt][2 * half + 1];
                    __nv_bfloat16 h0 = __float2bfloat16(v0), h1 = __float2bfloat16(v1);
                    __nv_bfloat162 hp; hp.x = h0; hp.y = h1;
                    __nv_bfloat162 lp;
                    lp.x = __float2bfloat16(v0 - __bfloat162float(h0));
                    lp.y = __float2bfloat16(v1 - __bfloat162float(h1));
                    *(__nv_bfloat162*)&Ch[ob + (size_t)rr * DMODEL] = hp;
                    *(__nv_bfloat162*)&Cl[ob + (size_t)rr * DMODEL] = lp;
                }
            }
        }
}

// =================================================================
// Tensor-core flash attention, split-bf16.
// CTA: 128 queries x one (b,h).  8 warps x 16 q-rows.  K/V tiles 64.
// smem stage: KH|KL|VH|VL, rows padded to 144B.  2 stages.
// =================================================================
#define AT_ROW 144
#define AT_MAT (64 * AT_ROW)          // 9216
#define AT_STAGE (4 * AT_MAT)         // 36864
#define ASCALE 0.03125f

__global__ __launch_bounds__(256, 1) void attn_mma_kernel(
    const __nv_bfloat16* __restrict__ qkvh,
    const __nv_bfloat16* __restrict__ qkvl,
    __nv_bfloat16* __restrict__ oh, __nv_bfloat16* __restrict__ ol)
{
    extern __shared__ __align__(128) char smem[];
    const uint32_t sb = smem_u32(smem);
    const int tid = threadIdx.x;
    const int wid = tid >> 5, lane = tid & 31;
    const int q0 = (int)(gridDim.x - 1 - blockIdx.x) * 128;
    const int h = blockIdx.y, b = blockIdx.z;

    const size_t base = (size_t)(b * SDIM) * DMODEL + h * HDIM;
    const __nv_bfloat16* Qh = qkvh + base;
    const __nv_bfloat16* Ql = qkvl + base;
    const __nv_bfloat16* Kh = qkvh + SLOTSZ + base;
    const __nv_bfloat16* Kl = qkvl + SLOTSZ + base;
    const __nv_bfloat16* Vh = qkvh + 2 * SLOTSZ + base;
    const __nv_bfloat16* Vl = qkvl + 2 * SLOTSZ + base;

    // ---- stage Q through smem (stage 0 area), extract frags ----
#pragma unroll
    for (int i = 0; i < 4; i++) {
        int idx = tid + i * 256;               // 0..1023
        int r = idx >> 3, c = idx & 7;
        size_t go = (size_t)(q0 + r) * DMODEL + c * 8;
        uint32_t so = (uint32_t)(r * AT_ROW + c * 16);
        cp16(sb + so, Qh + go);
        cp16(sb + 128 * AT_ROW + so, Ql + go);
    }
    CP_COMMIT(); CP_WAIT0();
    __syncthreads();

    uint32_t qhf[4][4], qlf[4][4];
    {
        uint32_t qa = sb + (uint32_t)((wid * 16 + (lane & 15)) * AT_ROW)
                         + (uint32_t)((lane >> 4) * 16);
#pragma unroll
        for (int ks = 0; ks < 4; ks++) {
            ldm_x4(qhf[ks][0], qhf[ks][1], qhf[ks][2], qhf[ks][3], qa + ks * 32);
            ldm_x4(qlf[ks][0], qlf[ks][1], qlf[ks][2], qlf[ks][3],
                   qa + 128 * AT_ROW + ks * 32);
        }
    }
    __syncthreads();

    auto issue = [&](int it) {
        const int k0 = it * 64;
        const uint32_t st = sb + (uint32_t)((it & 1) * AT_STAGE);
#pragma unroll
        for (int i = 0; i < 2; i++) {
            int idx = tid + i * 256;           // 0..511
            int r = idx >> 3, c = idx & 7;
            size_t go = (size_t)(k0 + r) * DMODEL + c * 8;
            uint32_t so = (uint32_t)(r * AT_ROW + c * 16);
            cp16(st + 0 * AT_MAT + so, Kh + go);
            cp16(st + 1 * AT_MAT + so, Kl + go);
            cp16(st + 2 * AT_MAT + so, Vh + go);
            cp16(st + 3 * AT_MAT + so, Vl + go);
        }
        CP_COMMIT();
    };

    float m_r[2] = { -1e30f, -1e30f };
    float l_r[2] = { 0.f, 0.f };
    float oc[8][4];
#pragma unroll
    for (int j = 0; j < 8; j++)
#pragma unroll
        for (int v = 0; v < 4; v++) oc[j][v] = 0.f;

    const int niters = (q0 >> 6) + 2;
    issue(0);
    if (niters > 1) issue(1);

    const int r0g = q0 + wid * 16 + (lane >> 2);
    const int r1g = r0g + 8;
    const int wrow_max = q0 + wid * 16 + 15;

    for (int it = 0; it < niters; it++) {
        if (it + 1 < niters) CP_WAIT1(); else CP_WAIT0();
        __syncthreads();
        const int k0 = it * 64;

        if (k0 <= wrow_max) {
            const uint32_t st = sb + (uint32_t)((it & 1) * AT_STAGE);
            const uint32_t kHi = st + (uint32_t)((lane & 15) * AT_ROW)
                                    + (uint32_t)((lane >> 4) * 16);
            const uint32_t kLo = kHi + AT_MAT;
            const uint32_t vHi = st + 2 * AT_MAT + (uint32_t)((lane & 15) * AT_ROW)
                                    + (uint32_t)((lane >> 4) * 16);
            const uint32_t vLo = vHi + AT_MAT;

            // ---- S = Q @ K^T (split) ----
            float sc[8][4];
#pragma unroll
            for (int j = 0; j < 8; j++)
#pragma unroll
                for (int v = 0; v < 4; v++) sc[j][v] = 0.f;

#pragma unroll
            for (int ks = 0; ks < 4; ks++) {
                uint32_t bh[8][2], bl[8][2];
#pragma unroll
                for (int g = 0; g < 4; g++) {
                    uint32_t r0, r1, r2, r3;
                    ldm_x4(r0, r1, r2, r3, kHi + (uint32_t)(g * 16 * AT_ROW) + ks * 32);
                    bh[2 * g + 0][0] = r0; bh[2 * g + 0][1] = r2;
                    bh[2 * g + 1][0] = r1; bh[2 * g + 1][1] = r3;
                    ldm_x4(r0, r1, r2, r3, kLo + (uint32_t)(g * 16 * AT_ROW) + ks * 32);
                    bl[2 * g + 0][0] = r0; bl[2 * g + 0][1] = r2;
                    bl[2 * g + 1][0] = r1; bl[2 * g + 1][1] = r3;
                }
#pragma unroll
                for (int j = 0; j < 8; j++) {
                    mma_bf16(sc[j], qhf[ks], bh[j][0], bh[j][1]);
                    mma_bf16(sc[j], qhf[ks], bl[j][0], bl[j][1]);
                    mma_bf16(sc[j], qlf[ks], bh[j][0], bh[j][1]);
                }
            }

            // ---- mask + scale ----
            const int cb = k0 + 2 * (lane & 3);
#pragma unroll
            for (int j = 0; j < 8; j++) {
                int c0 = cb + 8 * j, c1 = c0 + 1;
                sc[j][0] = (c0 <= r0g) ? sc[j][0] * ASCALE : -1e30f;
                sc[j][1] = (c1 <= r0g) ? sc[j][1] * ASCALE : -1e30f;
                sc[j][2] = (c0 <= r1g) ? sc[j][2] * ASCALE : -1e30f;
                sc[j][3] = (c1 <= r1g) ? sc[j][3] * ASCALE : -1e30f;
            }

            // ---- online softmax ----
            float mt0 = -1e30f, mt1 = -1e30f;
#pragma unroll
            for (int j = 0; j < 8; j++) {
                mt0 = fmaxf(mt0, fmaxf(sc[j][0], sc[j][1]));
                mt1 = fmaxf(mt1, fmaxf(sc[j][2], sc[j][3]));
            }
            mt0 = fmaxf(mt0, __shfl_xor_sync(0xffffffffu, mt0, 1));
            mt0 = fmaxf(mt0, __shfl_xor_sync(0xffffffffu, mt0, 2));
            mt1 = fmaxf(mt1, __shfl_xor_sync(0xffffffffu, mt1, 1));
            mt1 = fmaxf(mt1, __shfl_xor_sync(0xffffffffu, mt1, 2));
            float mn0 = fmaxf(m_r[0], mt0), mn1 = fmaxf(m_r[1], mt1);
            float a0 = __expf(m_r[0] - mn0), a1 = __expf(m_r[1] - mn1);
            m_r[0] = mn0; m_r[1] = mn1;

            float s0 = 0.f, s1 = 0.f;
#pragma unroll
            for (int j = 0; j < 8; j++) {
                sc[j][0] = __expf(sc[j][0] - mn0);
                sc[j][1] = __expf(sc[j][1] - mn0);
                sc[j][2] = __expf(sc[j][2] - mn1);
                sc[j][3] = __expf(sc[j][3] - mn1);
                s0 += sc[j][0] + sc[j][1];
                s1 += sc[j][2] + sc[j][3];
            }
            l_r[0] = l_r[0] * a0 + s0;
            l_r[1] = l_r[1] * a1 + s1;
#pragma unroll
            for (int j = 0; j < 8; j++) {
                oc[j][0] *= a0; oc[j][1] *= a0;
                oc[j][2] *= a1; oc[j][3] *= a1;
            }

            // ---- pack P (hi/lo) ----
            uint32_t ph[8][2], pl[8][2];
#pragma unroll
            for (int j = 0; j < 8; j++) {
                float f0 = __bfloat162float(__float2bfloat16(sc[j][0]));
                float f1 = __bfloat162float(__float2bfloat16(sc[j][1]));
                float f2 = __bfloat162float(__float2bfloat16(sc[j][2]));
                float f3 = __bfloat162float(__float2bfloat16(sc[j][3]));
                ph[j][0] = packbf(f0, f1);
                ph[j][1] = packbf(f2, f3);
                pl[j][0] = packbf(sc[j][0] - f0, sc[j][1] - f1);
                pl[j][1] = packbf(sc[j][2] - f2, sc[j][3] - f3);
            }

            // ---- O += P @ V (split) ----
#pragma unroll
            for (int ks = 0; ks < 4; ks++) {
                uint32_t vh[8][2], vl[8][2];
#pragma unroll
                for (int g = 0; g < 4; g++) {
                    uint32_t r0, r1, r2, r3;
                    ldm_x4t(r0, r1, r2, r3, vHi + (uint32_t)(ks * 16 * AT_ROW) + g * 32);
                    vh[2 * g + 0][0] = r0; vh[2 * g + 0][1] = r1;
                    vh[2 * g + 1][0] = r2; vh[2 * g + 1][1] = r3;
                    ldm_x4t(r0, r1, r2, r3, vLo + (uint32_t)(ks * 16 * AT_ROW) + g * 32);
                    vl[2 * g + 0][0] = r0; vl[2 * g + 0][1] = r1;
                    vl[2 * g + 1][0] = r2; vl[2 * g + 1][1] = r3;
                }
                uint32_t pah[4] = { ph[2 * ks][0], ph[2 * ks][1],
                                    ph[2 * ks + 1][0], ph[2 * ks + 1][1] };
                uint32_t pal[4] = { pl[2 * ks][0], pl[2 * ks][1],
                                    pl[2 * ks + 1][0], pl[2 * ks + 1][1] };
#pragma unroll
                for (int j = 0; j < 8; j++) {
                    mma_bf16(oc[j], pah, vh[j][0], vh[j][1]);
                    mma_bf16(oc[j], pah, vl[j][0], vl[j][1]);
                    mma_bf16(oc[j], pal, vh[j][0], vh[j][1]);
                }
            }
        }

        __syncthreads();
        if (it + 2 < niters) issue(it + 2);
    }

    // ---- epilogue ----
    float lt0 = l_r[0];
    lt0 += __shfl_xor_sync(0xffffffffu, lt0, 1);
    lt0 += __shfl_xor_sync(0xffffffffu, lt0, 2);
    float lt1 = l_r[1];
    lt1 += __shfl_xor_sync(0xffffffffu, lt1, 1);
    lt1 += __shfl_xor_sync(0xffffffffu, lt1, 2);
    float inv0 = 1.f / lt0, inv1 = 1.f / lt1;

    size_t ob0 = (size_t)(b * SDIM + r0g) * DMODEL + h * HDIM + 2 * (lane & 3);
    size_t ob1 = ob0 + (size_t)8 * DMODEL;
#pragma unroll
    for (int j = 0; j < 8; j++) {
        float v0 = oc[j][0] * inv0, v1 = oc[j][1] * inv0;
        float v2 = oc[j][2] * inv1, v3 = oc[j][3] * inv1;
        __nv_bfloat16 h0 = __float2bfloat16(v0), h1 = __float2bfloat16(v1);
        __nv_bfloat16 h2 = __float2bfloat16(v2), h3 = __float2bfloat16(v3);
        __nv_bfloat162 hp0; hp0.x = h0; hp0.y = h1;
        __nv_bfloat162 hp1; hp1.x = h2; hp1.y = h3;
        __nv_bfloat162 lp0, lp1;
        lp0.x = __float2bfloat16(v0 - __bfloat162float(h0));
        lp0.y = __float2bfloat16(v1 - __bfloat162float(h1));
        lp1.x = __float2bfloat16(v2 - __bfloat162float(h2));
        lp1.y = __float2bfloat16(v3 - __bfloat162float(h3));
        *(__nv_bfloat162*)&oh[ob0 + 8 * j] = hp0;
        *(__nv_bfloat162*)&ol[ob0 + 8 * j] = lp0;
        *(__nv_bfloat162*)&oh[ob1 + 8 * j] = hp1;
        *(__nv_bfloat162*)&ol[ob1 + 8 * j] = lp1;
    }
}

// =================================================================
extern "C" void kernel_launch(void* const* d_in, const int* in_sizes, int n_in,
                              void* d_out, int out_size)
{
    const float* x  = (const float*)d_in[0];
    const float* Wq = (const float*)d_in[1];
    const float* Wk = (const float*)d_in[2];
    const float* Wv = (const float*)d_in[3];
    const float* Wo = (const float*)d_in[4];
    const float* bo = (const float*)d_in[5];
    float* out = (float*)d_out;

    __nv_bfloat16 *pxh, *pxl, *pqkvh, *pqkvl, *pah, *pal, *pwh, *pwl;
    cudaGetSymbolAddress((void**)&pxh, g_xhi);
    cudaGetSymbolAddress((void**)&pxl, g_xlo);
    cudaGetSymbolAddress((void**)&pqkvh, g_qkvh);
    cudaGetSymbolAddress((void**)&pqkvl, g_qkvl);
    cudaGetSymbolAddress((void**)&pah, g_ah);
    cudaGetSymbolAddress((void**)&pal, g_al);
    cudaGetSymbolAddress((void**)&pwh, g_whi);
    cudaGetSymbolAddress((void**)&pwl, g_wlo);

    const int NEL = MTOT * DMODEL;
    const int WEL = DMODEL * DMODEL;

    split_kernel<<<NEL / (256 * 4), 256>>>(x, pxh, pxl, NEL);
    dim3 tgrid(DMODEL / 32, DMODEL / 32), tblk(32, 8);
    tsplit_kernel<<<tgrid, tblk>>>(Wq, pwh + 0 * WEL, pwl + 0 * WEL);
    tsplit_kernel<<<tgrid, tblk>>>(Wk, pwh + 1 * WEL, pwl + 1 * WEL);
    tsplit_kernel<<<tgrid, tblk>>>(Wv, pwh + 2 * WEL, pwl + 2 * WEL);
    tsplit_kernel<<<tgrid, tblk>>>(Wo, pwh + 3 * WEL, pwl + 3 * WEL);

    const int gsmem = 2 * ST_SZ;
    cudaFuncSetAttribute(gemm_mma_kernel<0>,
                         cudaFuncAttributeMaxDynamicSharedMemorySize, gsmem);
    cudaFuncSetAttribute(gemm_mma_kernel<1>,
                         cudaFuncAttributeMaxDynamicSharedMemorySize, gsmem);

    // fused QKV projection: N = 3072, epilogue writes split bf16
    dim3 gq(3 * DMODEL / 64, MTOT / 128);   // (48, 32)
    gemm_mma_kernel<1><<<gq, 256, gsmem>>>(pxh, pxl, pwh, pwl,
                                           nullptr, nullptr, pqkvh, pqkvl,
                                           MTOT, 3 * DMODEL, DMODEL);

    const int asmem = 2 * AT_STAGE;         // 73728
    cudaFuncSetAttribute(attn_mma_kernel,
                         cudaFuncAttributeMaxDynamicSharedMemorySize, asmem);
    dim3 agrid(SDIM / 128, NHEADS, BATCH);  // (16, 16, 2)
    attn_mma_kernel<<<agrid, 256, asmem>>>(pqkvh, pqkvl, pah, pal);

    dim3 go(DMODEL / 64, MTOT / 128);       // (16, 32)
    gemm_mma_kernel<0><<<go, 256, gsmem>>>(pah, pal, pwh + 3 * WEL, pwl + 3 * WEL,
                                           bo, out, nullptr, nullptr,
                                           MTOT, DMODEL, DMODEL);
}